// round 1
// baseline (speedup 1.0000x reference)
#include <cuda_runtime.h>

#define B_ 64
#define T_ 512
#define D_ 64
#define NT 511  // smoothing steps (t = 0..510)

// Scratch for G^T per (b,t):  64 * 511 * 64 * 64 floats = 536 MB
__device__ float g_GT[(size_t)B_ * NT * D_ * D_];

// ---------------------------------------------------------------------------
// 64x64x64 matmul accumulate core. 256 threads as 16x16 grid, 4x4 tile each.
// MODE 0: acc += A * B^T      (C[i][j] += sum_k A[i][k]*B[j][k])
// MODE 1: acc += A * B        (C[i][j] += sum_k A[i][k]*B[k][j])
// MODE 2: acc += A^T * B      (C[i][j] += sum_k A[k][i]*B[k][j])
// ---------------------------------------------------------------------------
template <int MODE>
__device__ __forceinline__ void mm_acc(const float* __restrict__ A,
                                       const float* __restrict__ Bm,
                                       float acc[4][4], int tx, int ty)
{
#pragma unroll 4
    for (int kq = 0; kq < 16; ++kq) {
        if (MODE == 0) {
            float a[4][4], b[4][4];
#pragma unroll
            for (int r = 0; r < 4; ++r)
                *(float4*)a[r] = *(const float4*)(A + (ty * 4 + r) * 64 + kq * 4);
#pragma unroll
            for (int c = 0; c < 4; ++c)
                *(float4*)b[c] = *(const float4*)(Bm + (tx * 4 + c) * 64 + kq * 4);
#pragma unroll
            for (int r = 0; r < 4; ++r)
#pragma unroll
                for (int c = 0; c < 4; ++c)
#pragma unroll
                    for (int q = 0; q < 4; ++q)
                        acc[r][c] += a[r][q] * b[c][q];
        } else if (MODE == 1) {
            float a[4][4], b[4][4];
#pragma unroll
            for (int r = 0; r < 4; ++r)
                *(float4*)a[r] = *(const float4*)(A + (ty * 4 + r) * 64 + kq * 4);
#pragma unroll
            for (int q = 0; q < 4; ++q)
                *(float4*)b[q] = *(const float4*)(Bm + (kq * 4 + q) * 64 + tx * 4);
#pragma unroll
            for (int r = 0; r < 4; ++r)
#pragma unroll
                for (int c = 0; c < 4; ++c)
#pragma unroll
                    for (int q = 0; q < 4; ++q)
                        acc[r][c] += a[r][q] * b[q][c];
        } else {
            float a[4][4], b[4][4];
#pragma unroll
            for (int q = 0; q < 4; ++q)
                *(float4*)a[q] = *(const float4*)(A + (kq * 4 + q) * 64 + ty * 4);
#pragma unroll
            for (int q = 0; q < 4; ++q)
                *(float4*)b[q] = *(const float4*)(Bm + (kq * 4 + q) * 64 + tx * 4);
#pragma unroll
            for (int r = 0; r < 4; ++r)
#pragma unroll
                for (int c = 0; c < 4; ++c)
#pragma unroll
                    for (int q = 0; q < 4; ++q)
                        acc[r][c] += a[q][r] * b[q][c];
        }
    }
}

// ---------------------------------------------------------------------------
// Phase 1: per (b, t) compute G_t, C_t, b_t  (independent, full-chip parallel)
//   T1 = Pi * F^T
//   Pp = F * T1 + Q            (SPD)
//   Cholesky Pp = L L^T, solve  GT = Pp^{-1} * T1^T   (GT[k][j] = G[j][k])
//   C  = Pi - T1 * GT          -> staged into ps_out[b][t]
//   b  = xi - G * (F xi)       -> staged into xs_out[b][t]
//   GT -> g_GT scratch
// Block t == 511 just copies the terminal state (xs=xf, Ps=Pf).
// ---------------------------------------------------------------------------
extern __shared__ float smem[];

__global__ void __launch_bounds__(256, 2) rts_phase1(
    const float* __restrict__ xf, const float* __restrict__ Pf,
    const float* __restrict__ F, const float* __restrict__ Q,
    float* __restrict__ xs_out, float* __restrict__ ps_out)
{
    const int t = blockIdx.x;   // 0..511
    const int b = blockIdx.y;
    const int tid = threadIdx.x;
    const size_t off = (size_t)b * T_ + t;

    const float* Pi_g = Pf + off * (D_ * D_);
    const float* xi_g = xf + off * D_;
    float* ps_o = ps_out + off * (D_ * D_);
    float* xs_o = xs_out + off * D_;

    if (t == T_ - 1) {
        const float4* src = (const float4*)Pi_g;
        float4* dst = (float4*)ps_o;
        for (int idx = tid; idx < 1024; idx += 256) dst[idx] = src[idx];
        if (tid < 64) xs_o[tid] = xi_g[tid];
        return;
    }

    float* sF   = smem;
    float* sPi  = smem + 4096;
    float* sT1  = smem + 2 * 4096;
    float* sPp  = smem + 3 * 4096;
    float* sR   = smem + 4 * 4096;
    float* sInv = smem + 5 * 4096;
    float* sXi  = sInv + 64;
    float* sXp  = sXi + 64;

    // Load F, Pi, xi
    for (int idx = tid; idx < 1024; idx += 256) {
        ((float4*)sF)[idx]  = ((const float4*)F)[idx];
        ((float4*)sPi)[idx] = ((const float4*)Pi_g)[idx];
    }
    if (tid < 64) sXi[tid] = xi_g[tid];
    __syncthreads();

    const int tx = tid & 15, ty = tid >> 4;

    // T1 = Pi * F^T
    {
        float acc[4][4] = {};
        mm_acc<0>(sPi, sF, acc, tx, ty);
#pragma unroll
        for (int r = 0; r < 4; ++r)
            *(float4*)(sT1 + (ty * 4 + r) * 64 + tx * 4) = *(float4*)acc[r];
    }
    // xp = F * xi (independent of T1)
    if (tid < 64) {
        float a = 0.f;
#pragma unroll 8
        for (int k = 0; k < 64; ++k) a += sF[tid * 64 + k] * sXi[k];
        sXp[tid] = a;
    }
    __syncthreads();

    // Pp = F * T1 + Q ;  sR = T1^T
    {
        float acc[4][4] = {};
        mm_acc<1>(sF, sT1, acc, tx, ty);
#pragma unroll
        for (int r = 0; r < 4; ++r) {
            float4 q4 = *(const float4*)(Q + (ty * 4 + r) * 64 + tx * 4);
            float4 o;
            o.x = acc[r][0] + q4.x; o.y = acc[r][1] + q4.y;
            o.z = acc[r][2] + q4.z; o.w = acc[r][3] + q4.w;
            *(float4*)(sPp + (ty * 4 + r) * 64 + tx * 4) = o;
        }
    }
    for (int idx = tid; idx < 4096; idx += 256) {
        int k = idx >> 6, j = idx & 63;
        sR[idx] = sT1[j * 64 + k];
    }
    __syncthreads();

    // In-place Cholesky (lower) of sPp, store 1/L[k][k]
    for (int k = 0; k < 64; ++k) {
        if (tid == 0) {
            float d = sPp[k * 64 + k];
            float s = sqrtf(d);
            sInv[k] = 1.0f / s;
        }
        __syncthreads();
        float rinv = sInv[k];
        if (tid < 64 - k) sPp[(k + tid) * 64 + k] *= rinv;
        __syncthreads();
        int nrows = 63 - k;
        for (int idx = tid; idx < nrows * 64; idx += 256) {
            int i = k + 1 + (idx >> 6);
            int j = idx & 63;
            if (j > k && j <= i)
                sPp[i * 64 + j] -= sPp[i * 64 + k] * sPp[j * 64 + k];
        }
        __syncthreads();
    }

    // Forward solve: L Y = R (in place)
    for (int k = 0; k < 64; ++k) {
        if (tid < 64) sR[k * 64 + tid] *= sInv[k];
        __syncthreads();
        int nrows = 63 - k;
        for (int idx = tid; idx < nrows * 64; idx += 256) {
            int i = k + 1 + (idx >> 6), j = idx & 63;
            sR[i * 64 + j] -= sPp[i * 64 + k] * sR[k * 64 + j];
        }
        __syncthreads();
    }
    // Backward solve: L^T GT = Y (in place)
    for (int k = 63; k >= 0; --k) {
        if (tid < 64) sR[k * 64 + tid] *= sInv[k];
        __syncthreads();
        for (int idx = tid; idx < k * 64; idx += 256) {
            int i = idx >> 6, j = idx & 63;
            sR[i * 64 + j] -= sPp[k * 64 + i] * sR[k * 64 + j];
        }
        __syncthreads();
    }

    // GT -> scratch
    {
        float4* gdst = (float4*)(g_GT + ((size_t)b * NT + t) * 4096);
        for (int idx = tid; idx < 1024; idx += 256)
            gdst[idx] = ((float4*)sR)[idx];
    }

    // C = Pi - T1 * GT -> ps_out (staged)
    {
        float acc[4][4] = {};
        mm_acc<1>(sT1, sR, acc, tx, ty);
#pragma unroll
        for (int r = 0; r < 4; ++r) {
            float4 pi4 = *(const float4*)(sPi + (ty * 4 + r) * 64 + tx * 4);
            float4 o;
            o.x = pi4.x - acc[r][0]; o.y = pi4.y - acc[r][1];
            o.z = pi4.z - acc[r][2]; o.w = pi4.w - acc[r][3];
            *(float4*)(ps_o + (ty * 4 + r) * 64 + tx * 4) = o;
        }
    }
    // b = xi - G * xp -> xs_out (staged)
    if (tid < 64) {
        float a = 0.f;
#pragma unroll 8
        for (int k = 0; k < 64; ++k) a += sR[k * 64 + tid] * sXp[k];
        xs_o[tid] = sXi[tid] - a;
    }
}

// ---------------------------------------------------------------------------
// Phase 2: per batch, sequential backward affine scan:
//   Ps_t = C_t + G Ps_{t+1} G^T        (2 matmuls: W = G*Ps; Ps = C + W*G^T)
//   xs_t = b_t + G xs_{t+1}
// C_t / b_t are read from the output buffer and overwritten in place.
// ---------------------------------------------------------------------------
__global__ void __launch_bounds__(256, 1) rts_phase2(
    float* __restrict__ xs_out, float* __restrict__ ps_out)
{
    const int b = blockIdx.x;
    const int tid = threadIdx.x;
    const int tx = tid & 15, ty = tid >> 4;

    float* sPs  = smem;
    float* sGT  = smem + 4096;
    float* sW   = smem + 2 * 4096;
    float* sXs  = smem + 3 * 4096;
    float* sXs2 = sXs + 64;

    // Init with terminal state
    {
        const float4* src = (const float4*)(ps_out + ((size_t)b * T_ + (T_ - 1)) * 4096);
        for (int idx = tid; idx < 1024; idx += 256) ((float4*)sPs)[idx] = src[idx];
        if (tid < 64) sXs[tid] = xs_out[((size_t)b * T_ + (T_ - 1)) * 64 + tid];
    }
    __syncthreads();

    for (int t = T_ - 2; t >= 0; --t) {
        const float4* gGT = (const float4*)(g_GT + ((size_t)b * NT + t) * 4096);
        for (int idx = tid; idx < 1024; idx += 256) ((float4*)sGT)[idx] = gGT[idx];
        __syncthreads();

        // W = G * Ps_prev  (G[i][k] = GT[k][i])
        {
            float acc[4][4] = {};
            mm_acc<2>(sGT, sPs, acc, tx, ty);
#pragma unroll
            for (int r = 0; r < 4; ++r)
                *(float4*)(sW + (ty * 4 + r) * 64 + tx * 4) = *(float4*)acc[r];
        }
        // xs_new = b + G * xs_prev
        if (tid < 64) {
            float a = xs_out[((size_t)b * T_ + t) * 64 + tid];
#pragma unroll 8
            for (int k = 0; k < 64; ++k) a += sGT[k * 64 + tid] * sXs[k];
            sXs2[tid] = a;
        }
        __syncthreads();

        // Ps_new = C + W * G^T  -> gmem and sPs
        {
            float* ps_o = ps_out + ((size_t)b * T_ + t) * 4096;
            float4 cv[4];
#pragma unroll
            for (int r = 0; r < 4; ++r)
                cv[r] = *(const float4*)(ps_o + (ty * 4 + r) * 64 + tx * 4);
            float acc[4][4] = {};
            mm_acc<1>(sW, sGT, acc, tx, ty);
#pragma unroll
            for (int r = 0; r < 4; ++r) {
                float4 o;
                o.x = cv[r].x + acc[r][0]; o.y = cv[r].y + acc[r][1];
                o.z = cv[r].z + acc[r][2]; o.w = cv[r].w + acc[r][3];
                *(float4*)(ps_o + (ty * 4 + r) * 64 + tx * 4) = o;
                *(float4*)(sPs + (ty * 4 + r) * 64 + tx * 4) = o;
            }
        }
        if (tid < 64) {
            float v = sXs2[tid];
            sXs[tid] = v;
            xs_out[((size_t)b * T_ + t) * 64 + tid] = v;
        }
        __syncthreads();
    }
}

// ---------------------------------------------------------------------------
extern "C" void kernel_launch(void* const* d_in, const int* in_sizes, int n_in,
                              void* d_out, int out_size)
{
    const float* xf = (const float*)d_in[0];
    const float* Pf = (const float*)d_in[1];
    const float* F  = (const float*)d_in[2];
    const float* Q  = (const float*)d_in[3];

    float* out = (float*)d_out;
    float* xs_out = out;                                 // B*T*D floats
    float* ps_out = out + (size_t)B_ * T_ * D_;          // B*T*D*D floats

    const size_t sm1 = (size_t)(5 * 4096 + 3 * 64) * sizeof(float);  // 82,688 B
    const size_t sm2 = (size_t)(3 * 4096 + 2 * 64) * sizeof(float);  // 49,664 B

    cudaFuncSetAttribute(rts_phase1, cudaFuncAttributeMaxDynamicSharedMemorySize, (int)sm1);
    cudaFuncSetAttribute(rts_phase2, cudaFuncAttributeMaxDynamicSharedMemorySize, (int)sm2);

    dim3 g1(T_, B_);
    rts_phase1<<<g1, 256, sm1>>>(xf, Pf, F, Q, xs_out, ps_out);
    rts_phase2<<<B_, 256, sm2>>>(xs_out, ps_out);
}

// round 17
// speedup vs baseline: 2.6760x; 2.6760x over previous
#include <cuda_runtime.h>
#include <math.h>

#define B_ 64
#define T_ 512
#define D_ 64
#define NT 511  // smoothing steps (t = 0..510)

// Scratch for G^T per (b,t):  64 * 511 * 64 * 64 floats = 536 MB
__device__ float g_GT[(size_t)B_ * NT * D_ * D_];

// ---------------------------------------------------------------------------
// 64x64x64 matmul accumulate core. Threads as 16x16 grid, 4x4 tile each.
// MODE 0: acc += A * B^T      (C[i][j] += sum_k A[i][k]*B[j][k])
// MODE 1: acc += A * B        (C[i][j] += sum_k A[i][k]*B[k][j])
// MODE 2: acc += A^T * B      (C[i][j] += sum_k A[k][i]*B[k][j])
// SA/SB: row strides (in floats) of A and B.
// ---------------------------------------------------------------------------
template <int MODE, int SA, int SB>
__device__ __forceinline__ void mm_acc(const float* __restrict__ A,
                                       const float* __restrict__ Bm,
                                       float acc[4][4], int tx, int ty)
{
#pragma unroll 4
    for (int kq = 0; kq < 16; ++kq) {
        if (MODE == 0) {
            float a[4][4], b[4][4];
#pragma unroll
            for (int r = 0; r < 4; ++r)
                *(float4*)a[r] = *(const float4*)(A + (ty * 4 + r) * SA + kq * 4);
#pragma unroll
            for (int c = 0; c < 4; ++c)
                *(float4*)b[c] = *(const float4*)(Bm + (tx * 4 + c) * SB + kq * 4);
#pragma unroll
            for (int r = 0; r < 4; ++r)
#pragma unroll
                for (int c = 0; c < 4; ++c)
#pragma unroll
                    for (int q = 0; q < 4; ++q)
                        acc[r][c] += a[r][q] * b[c][q];
        } else if (MODE == 1) {
            float a[4][4], b[4][4];
#pragma unroll
            for (int r = 0; r < 4; ++r)
                *(float4*)a[r] = *(const float4*)(A + (ty * 4 + r) * SA + kq * 4);
#pragma unroll
            for (int q = 0; q < 4; ++q)
                *(float4*)b[q] = *(const float4*)(Bm + (kq * 4 + q) * SB + tx * 4);
#pragma unroll
            for (int r = 0; r < 4; ++r)
#pragma unroll
                for (int c = 0; c < 4; ++c)
#pragma unroll
                    for (int q = 0; q < 4; ++q)
                        acc[r][c] += a[r][q] * b[q][c];
        } else {
            float a[4][4], b[4][4];
#pragma unroll
            for (int q = 0; q < 4; ++q)
                *(float4*)a[q] = *(const float4*)(A + (kq * 4 + q) * SA + ty * 4);
#pragma unroll
            for (int q = 0; q < 4; ++q)
                *(float4*)b[q] = *(const float4*)(Bm + (kq * 4 + q) * SB + tx * 4);
#pragma unroll
            for (int r = 0; r < 4; ++r)
#pragma unroll
                for (int c = 0; c < 4; ++c)
#pragma unroll
                    for (int q = 0; q < 4; ++q)
                        acc[r][c] += a[q][r] * b[q][c];
        }
    }
}

// ---------------------------------------------------------------------------
// Phase 1: per (b, t) compute G_t, C_t, b_t  (independent, full-chip parallel)
//   T1^T = F * Pi                    (Pi symmetric => T1 = Pi F^T)
//   Pp   = T1^T * F^T + Q            (SPD)
//   Blocked Gauss-Jordan (4-wide panels) on [Pp | T1^T] -> [I | GT],
//     GT = Pp^{-1} T1^T = G^T.  Rank-4 updates, 3 barriers/panel (48 total).
//   C    = Pi - (T1^T)^T * GT   -> staged into ps_out[b][t]
//   bvec = xi - G * (F xi)      -> staged into xs_out[b][t]
//   GT -> g_GT scratch
// Block t == 511 copies the terminal state (xs=xf, Ps=Pf).
// smem: sPi(4096)+sT1t(4096)+sAug(8192)+sPR(512)+sInv4(16)+vecs(128)
//       = 17040 floats = 68160 B -> occupancy 3
// ---------------------------------------------------------------------------
extern __shared__ float smem[];

__global__ void __launch_bounds__(256, 3) rts_phase1(
    const float* __restrict__ xf, const float* __restrict__ Pf,
    const float* __restrict__ F, const float* __restrict__ Q,
    float* __restrict__ xs_out, float* __restrict__ ps_out)
{
    const int t = blockIdx.x;   // 0..511
    const int b = blockIdx.y;
    const int tid = threadIdx.x;
    const size_t off = (size_t)b * T_ + t;

    const float* Pi_g = Pf + off * (D_ * D_);
    const float* xi_g = xf + off * D_;
    float* ps_o = ps_out + off * (D_ * D_);
    float* xs_o = xs_out + off * D_;

    if (t == T_ - 1) {
        const float4* src = (const float4*)Pi_g;
        float4* dst = (float4*)ps_o;
        for (int idx = tid; idx < 1024; idx += 256) dst[idx] = src[idx];
        if (tid < 64) xs_o[tid] = xi_g[tid];
        return;
    }

    float* sPi   = smem;                 // 4096, stride 64
    float* sT1t  = smem + 4096;          // 4096, stride 64
    float* sAug  = smem + 2 * 4096;      // 64 x 128
    float* sPR   = sAug + 8192;          // 4 x 128 transformed pivot rows
    float* sInv4 = sPR + 512;            // 16
    float* sXi   = sInv4 + 16;           // 64
    float* sXp   = sXi + 64;             // 64

    // Load Pi, xi into smem
    for (int idx = tid; idx < 1024; idx += 256)
        ((float4*)sPi)[idx] = ((const float4*)Pi_g)[idx];
    if (tid < 64) sXi[tid] = xi_g[tid];
    __syncthreads();

    const int tx = tid & 15, ty = tid >> 4;

    // T1^T = F * Pi  -> sT1t and aug right half
    {
        float acc[4][4] = {};
        mm_acc<1, 64, 64>(F, sPi, acc, tx, ty);
#pragma unroll
        for (int r = 0; r < 4; ++r) {
            *(float4*)(sT1t + (ty * 4 + r) * 64 + tx * 4) = *(float4*)acc[r];
            *(float4*)(sAug + (ty * 4 + r) * 128 + 64 + tx * 4) = *(float4*)acc[r];
        }
    }
    // xp = F * xi  (F via L1-cached gmem)
    if (tid < 64) {
        float a = 0.f;
#pragma unroll 8
        for (int k = 0; k < 64; ++k) a += __ldg(F + tid * 64 + k) * sXi[k];
        sXp[tid] = a;
    }
    __syncthreads();

    // Pp = T1^T * F^T + Q  -> aug left half
    {
        float acc[4][4] = {};
        mm_acc<0, 64, 64>(sT1t, F, acc, tx, ty);
#pragma unroll
        for (int r = 0; r < 4; ++r) {
            float4 q4 = __ldg((const float4*)(Q + (ty * 4 + r) * 64 + tx * 4));
            float4 o;
            o.x = acc[r][0] + q4.x; o.y = acc[r][1] + q4.y;
            o.z = acc[r][2] + q4.z; o.w = acc[r][3] + q4.w;
            *(float4*)(sAug + (ty * 4 + r) * 128 + tx * 4) = o;
        }
    }
    __syncthreads();

    // ---- Blocked Gauss-Jordan, 16 panels of width 4 ----
    // Invariant: multipliers for the rank-4 update are PRE-panel values of
    // A[i, panel cols]; transformed pivot rows go to sPR first, so sAug's
    // pivot rows and multiplier columns stay intact until the update phase.
#pragma unroll 1
    for (int p = 0; p < 16; ++p) {
        const int P0 = p * 4;

        // (a) invert 4x4 diagonal block (serial; hidden by occupancy)
        if (tid == 0) {
            float a[4][4], iv[4][4];
#pragma unroll
            for (int j = 0; j < 4; ++j)
#pragma unroll
                for (int k = 0; k < 4; ++k) {
                    a[j][k] = sAug[(P0 + j) * 128 + P0 + k];
                    iv[j][k] = (j == k) ? 1.f : 0.f;
                }
#pragma unroll
            for (int k = 0; k < 4; ++k) {
                float piv = 1.0f / a[k][k];
#pragma unroll
                for (int j = 0; j < 4; ++j) { a[k][j] *= piv; iv[k][j] *= piv; }
#pragma unroll
                for (int i = 0; i < 4; ++i) if (i != k) {
                    float m = a[i][k];
#pragma unroll
                    for (int j = 0; j < 4; ++j) {
                        a[i][j] -= m * a[k][j];
                        iv[i][j] -= m * iv[k][j];
                    }
                }
            }
#pragma unroll
            for (int j = 0; j < 4; ++j)
#pragma unroll
                for (int k = 0; k < 4; ++k) sInv4[j * 4 + k] = iv[j][k];
        }
        __syncthreads();

        // (b) PR = inv4 * pivot rows, live cols c >= P0
        if (tid < 128 && tid >= P0) {
            const int c = tid;
            float r0 = sAug[(P0 + 0) * 128 + c];
            float r1 = sAug[(P0 + 1) * 128 + c];
            float r2 = sAug[(P0 + 2) * 128 + c];
            float r3 = sAug[(P0 + 3) * 128 + c];
#pragma unroll
            for (int j = 0; j < 4; ++j)
                sPR[j * 128 + c] = sInv4[j * 4 + 0] * r0 + sInv4[j * 4 + 1] * r1
                                 + sInv4[j * 4 + 2] * r2 + sInv4[j * 4 + 3] * r3;
        }
        __syncthreads();

        // (c) rank-4 update of all rows, live col groups (c0 >= P0)
        {
            const int c0 = (tid & 31) * 4;
            if (c0 >= P0) {
                const float4 pk0 = *(const float4*)(sPR + 0 * 128 + c0);
                const float4 pk1 = *(const float4*)(sPR + 1 * 128 + c0);
                const float4 pk2 = *(const float4*)(sPR + 2 * 128 + c0);
                const float4 pk3 = *(const float4*)(sPR + 3 * 128 + c0);
                const int rbase = (tid >> 5) * 8;
#pragma unroll
                for (int r = 0; r < 8; ++r) {
                    const int i = rbase + r;
                    float* row = sAug + i * 128 + c0;
                    if (i >= P0 && i < P0 + 4) {
                        // pivot row: install transformed values
                        *(float4*)row = *(const float4*)(sPR + (i - P0) * 128 + c0);
                    } else if (c0 != P0) {
                        // multipliers: pre-panel values (broadcast reads)
                        const float m0 = sAug[i * 128 + P0 + 0];
                        const float m1 = sAug[i * 128 + P0 + 1];
                        const float m2 = sAug[i * 128 + P0 + 2];
                        const float m3 = sAug[i * 128 + P0 + 3];
                        float4 v = *(const float4*)row;
                        v.x -= m0 * pk0.x + m1 * pk1.x + m2 * pk2.x + m3 * pk3.x;
                        v.y -= m0 * pk0.y + m1 * pk1.y + m2 * pk2.y + m3 * pk3.y;
                        v.z -= m0 * pk0.z + m1 * pk1.z + m2 * pk2.z + m3 * pk3.z;
                        v.w -= m0 * pk0.w + m1 * pk1.w + m2 * pk2.w + m3 * pk3.w;
                        *(float4*)row = v;
                    }
                    // c0 == P0 && i not pivot: skip write (dead multiplier
                    // cols; others still read them as m this phase)
                }
            }
        }
        __syncthreads();
    }

    // GT (aug right half) -> scratch
    {
        float4* gdst = (float4*)(g_GT + ((size_t)b * NT + t) * 4096);
        for (int idx = tid; idx < 1024; idx += 256) {
            int row = idx >> 4, cq = idx & 15;
            gdst[idx] = *(const float4*)(sAug + row * 128 + 64 + cq * 4);
        }
    }

    // C = Pi - (T1^T)^T * GT  -> ps_out (staged)
    {
        float acc[4][4] = {};
        mm_acc<2, 64, 128>(sT1t, sAug + 64, acc, tx, ty);
#pragma unroll
        for (int r = 0; r < 4; ++r) {
            float4 pi4 = *(const float4*)(sPi + (ty * 4 + r) * 64 + tx * 4);
            float4 o;
            o.x = pi4.x - acc[r][0]; o.y = pi4.y - acc[r][1];
            o.z = pi4.z - acc[r][2]; o.w = pi4.w - acc[r][3];
            *(float4*)(ps_o + (ty * 4 + r) * 64 + tx * 4) = o;
        }
    }
    // bvec = xi - G * xp   (G[i][k] = GT[k][i])
    if (tid < 64) {
        float a = 0.f;
#pragma unroll 8
        for (int k = 0; k < 64; ++k) a += sAug[k * 128 + 64 + tid] * sXp[k];
        xs_o[tid] = sXi[tid] - a;
    }
}

// ---------------------------------------------------------------------------
// Phase 2: per batch, sequential backward affine scan:
//   Ps_t = C_t + G Ps_{t+1} G^T        (W = G*Ps; Ps = C + W*G^T)
//   xs_t = b_t + G xs_{t+1}
// Ps_new is SYMMETRIC: the second matmul computes only the 136 lower-triangle
// 4x4 tiles, remapped onto threads 0..135 (whole warps 5..7 idle -> real
// issue-slot savings), and mirrors results into the upper triangle. The
// C-addend for the mirror equals the original since C is symmetric.
// G^T tiles and the C/b inputs are prefetched (registers) ahead of the
// barrier that publishes the previous iteration's state.
// ---------------------------------------------------------------------------
__global__ void __launch_bounds__(256, 1) rts_phase2(
    float* __restrict__ xs_out, float* __restrict__ ps_out)
{
    const int b = blockIdx.x;
    const int tid = threadIdx.x;

    // Triangular tile decode for mm2: thread tid<136 -> tile (tyq, txq),
    // txq<=tyq. Integer fix-up guards against fast-math sqrt off-by-one.
    int tyq = 0, txq = 0;
    if (tid < 136) {
        float s = sqrtf(8.0f * (float)tid + 1.0f);
        tyq = (int)((s - 1.0f) * 0.5f);
        while (tyq * (tyq + 1) / 2 > tid) --tyq;
        while ((tyq + 1) * (tyq + 2) / 2 <= tid) ++tyq;
        txq = tid - tyq * (tyq + 1) / 2;
    }
    const int tx = tid & 15, ty = tid >> 4;  // full-grid mapping for mm1

    float* sPs  = smem;
    float* sGT  = smem + 4096;
    float* sW   = smem + 2 * 4096;
    float* sXs  = smem + 3 * 4096;
    float* sXs2 = sXs + 64;

    // Terminal state
    {
        const float4* src = (const float4*)(ps_out + ((size_t)b * T_ + (T_ - 1)) * 4096);
        for (int idx = tid; idx < 1024; idx += 256) ((float4*)sPs)[idx] = src[idx];
        if (tid < 64) sXs[tid] = xs_out[((size_t)b * T_ + (T_ - 1)) * 64 + tid];
    }

    // Prefetch GT(T-2) into registers
    float4 rb[4];
    {
        const float4* g = (const float4*)(g_GT + ((size_t)b * NT + (T_ - 2)) * 4096);
#pragma unroll
        for (int j = 0; j < 4; ++j) rb[j] = g[tid + 256 * j];
    }
    __syncthreads();

    for (int t = T_ - 2; t >= 0; --t) {
        // Commit prefetched GT to smem; immediately issue next prefetch
#pragma unroll
        for (int j = 0; j < 4; ++j) ((float4*)sGT)[tid + 256 * j] = rb[j];
        if (t > 0) {
            const float4* g = (const float4*)(g_GT + ((size_t)b * NT + (t - 1)) * 4096);
#pragma unroll
            for (int j = 0; j < 4; ++j) rb[j] = g[tid + 256 * j];
        }
        // Prefetch C tile (at the TRIANGULAR tile position) and b vector
        float* ps_o = ps_out + ((size_t)b * T_ + t) * 4096;
        float4 cv[4];
        if (tid < 136) {
#pragma unroll
            for (int r = 0; r < 4; ++r)
                cv[r] = *(const float4*)(ps_o + (tyq * 4 + r) * 64 + txq * 4);
        }
        float bvec = 0.f;
        if (tid < 64) bvec = xs_out[((size_t)b * T_ + t) * 64 + tid];
        __syncthreads();

        // W = G * Ps_prev  (G[i][k] = GT[k][i]) — full 16x16 tile grid
        {
            float acc[4][4] = {};
            mm_acc<2, 64, 64>(sGT, sPs, acc, tx, ty);
#pragma unroll
            for (int r = 0; r < 4; ++r)
                *(float4*)(sW + (ty * 4 + r) * 64 + tx * 4) = *(float4*)acc[r];
        }
        // xs_new = b + G * xs_prev
        if (tid < 64) {
            float a = bvec;
#pragma unroll 8
            for (int k = 0; k < 64; ++k) a += sGT[k * 64 + tid] * sXs[k];
            sXs2[tid] = a;
        }
        __syncthreads();

        // Ps_new = C + W * G^T  (symmetric) — lower-triangle tiles only
        if (tid < 136) {
            float acc[4][4] = {};
            mm_acc<1, 64, 64>(sW, sGT, acc, txq, tyq);
#pragma unroll
            for (int r = 0; r < 4; ++r) {
                float4 o;
                o.x = cv[r].x + acc[r][0]; o.y = cv[r].y + acc[r][1];
                o.z = cv[r].z + acc[r][2]; o.w = cv[r].w + acc[r][3];
                *(float4*)(ps_o + (tyq * 4 + r) * 64 + txq * 4) = o;
                *(float4*)(sPs + (tyq * 4 + r) * 64 + txq * 4) = o;
                if (txq < tyq) {
                    // mirror into upper triangle (C symmetric => same addend)
                    const int I = tyq * 4 + r;
                    ps_o[(txq * 4 + 0) * 64 + I] = o.x;
                    ps_o[(txq * 4 + 1) * 64 + I] = o.y;
                    ps_o[(txq * 4 + 2) * 64 + I] = o.z;
                    ps_o[(txq * 4 + 3) * 64 + I] = o.w;
                    sPs[(txq * 4 + 0) * 64 + I] = o.x;
                    sPs[(txq * 4 + 1) * 64 + I] = o.y;
                    sPs[(txq * 4 + 2) * 64 + I] = o.z;
                    sPs[(txq * 4 + 3) * 64 + I] = o.w;
                }
            }
        }
        if (tid < 64) {
            float v = sXs2[tid];
            sXs[tid] = v;
            xs_out[((size_t)b * T_ + t) * 64 + tid] = v;
        }
        __syncthreads();
    }
}

// ---------------------------------------------------------------------------
extern "C" void kernel_launch(void* const* d_in, const int* in_sizes, int n_in,
                              void* d_out, int out_size)
{
    const float* xf = (const float*)d_in[0];
    const float* Pf = (const float*)d_in[1];
    const float* F  = (const float*)d_in[2];
    const float* Q  = (const float*)d_in[3];

    float* out = (float*)d_out;
    float* xs_out = out;                                 // B*T*D floats
    float* ps_out = out + (size_t)B_ * T_ * D_;          // B*T*D*D floats

    const size_t sm1 = (size_t)(2 * 4096 + 8192 + 512 + 16 + 2 * 64) * sizeof(float); // 68,160 B
    const size_t sm2 = (size_t)(3 * 4096 + 2 * 64) * sizeof(float);                   // 49,664 B

    cudaFuncSetAttribute(rts_phase1, cudaFuncAttributeMaxDynamicSharedMemorySize, (int)sm1);
    cudaFuncSetAttribute(rts_phase2, cudaFuncAttributeMaxDynamicSharedMemorySize, (int)sm2);

    dim3 g1(T_, B_);
    rts_phase1<<<g1, 256, sm1>>>(xf, Pf, F, Q, xs_out, ps_out);
    rts_phase2<<<B_, 256, sm2>>>(xs_out, ps_out);
}